// round 1
// baseline (speedup 1.0000x reference)
#include <cuda_runtime.h>
#include <cmath>
#include <cstdint>

// ============================================================================
// Problem constants
// ============================================================================
#define NPTS   32768
#define NDATA  1024
#define NQUAD  1000
#define TOTALP (NPTS + NDATA + NQUAD + 2)   // 34794
#define NCHUNKS ((TOTALP + 7) / 8)          // 4350

static constexpr double kEI = 5.0e7 * (((0.02 * 0.02 * 0.02) * 0.02) / 12.0); // EI
static constexpr double kWC = 1.0 / kEI;                                       // W_C (X_C = 1)

// ============================================================================
// Device globals (scratch — no allocation allowed)
// ============================================================================
__device__ float g_tn[NQUAD];     // transformed quadrature nodes 0.5*x + 0.5 (f32)
__device__ float g_wsum;          // sum of f32 quadrature weights
__device__ float g_fsq[NQUAD];    // (w'')^2 at quadrature nodes
__device__ float g_pred[NDATA];   // MLP prediction at data points
__device__ float g_bdry[10];      // jets at s=0 (0..4) and s=1 (5..9)

// ============================================================================
// Host-side Gauss-Legendre nodes/weights (double Newton, static init — runs
// once at program load; NOT inside kernel_launch)
// ============================================================================
struct GLTables {
    float tn[NQUAD];
    float wsum;
    GLTables() {
        const int n = NQUAD;
        const double pi = 3.14159265358979323846;
        double sumw = 0.0;
        for (int k = 0; k < n; k++) {
            double x = cos(pi * (k + 0.75) / (n + 0.5));
            for (int it = 0; it < 100; it++) {
                double p0 = 1.0, p1 = x;
                for (int m = 2; m <= n; m++) {
                    double p2 = ((2.0 * m - 1.0) * x * p1 - (m - 1.0) * p0) / m;
                    p0 = p1; p1 = p2;
                }
                double dp = n * (x * p1 - p0) / (x * x - 1.0);
                double dx = p1 / dp;
                x -= dx;
                if (fabs(dx) < 1e-15) break;
            }
            // weight at converged x
            double p0 = 1.0, p1 = x;
            for (int m = 2; m <= n; m++) {
                double p2 = ((2.0 * m - 1.0) * x * p1 - (m - 1.0) * p0) / m;
                p0 = p1; p1 = p2;
            }
            double dp = n * (x * p1 - p0) / (x * x - 1.0);
            double w = 2.0 / ((1.0 - x * x) * dp * dp);
            sumw += (double)(float)w;                 // sum of f32-rounded weights
            tn[k] = (float)(0.5 * x + 0.5);
        }
        wsum = (float)sumw;
    }
};
static GLTables g_gl;   // static init, host side

// ============================================================================
// Shared memory layout (dynamic)
// ============================================================================
static constexpr int SM_HA4  = 0;                    // float4[8*128]  16384 B
static constexpr int SM_HB4  = 16384;                // float4[8*128]  16384 B
static constexpr int SM_HA1  = 32768;                // float [8*128]   4096 B
static constexpr int SM_HB1  = 36864;                // float [8*128]   4096 B
static constexpr int SM_W1   = 40960;                // float [16384]  65536 B
static constexpr int SM_W2   = 106496;               // float [16384]  65536 B
static constexpr int SM_W0   = 172032;               // float [128]      512 B
static constexpr int SM_W3   = 172544;               // float [128]      512 B
static constexpr int SM_B0   = 173056;               // float [128]      512 B
static constexpr int SM_B1   = 173568;               // float [128]      512 B
static constexpr int SM_B2   = 174080;               // float [128]      512 B
static constexpr int SM_B3   = 174592;               // float [1]         16 B
static constexpr int SM_SS   = 174608;               // float [8]         32 B
static constexpr int SM_RED  = 174640;               // float [8*5*4]    640 B
static constexpr int SM_DFIN = 175280;               // float [8*5]      160 B
static constexpr int SMEM_BYTES = 175440;

// ============================================================================
// tanh jet: given pre-activation jet (a0..a4), produce activation jet (y0..y4)
// via Faa di Bruno with tanh derivatives.
// ============================================================================
__device__ __forceinline__ void tanh_jet(float a0, float a1, float a2, float a3, float a4,
                                         float& y0, float& y1, float& y2, float& y3, float& y4)
{
    float t  = tanhf(a0);
    float t2 = t * t;
    float g1 = 1.0f - t2;                       // u'
    float u2 = -2.0f * t * g1;                  // u''
    float u3 = g1 * (6.0f * t2 - 2.0f);         // u'''
    float u4 = g1 * (16.0f * t - 24.0f * t2 * t); // u''''
    float a1s = a1 * a1;
    y0 = t;
    y1 = g1 * a1;
    y2 = u2 * a1s + g1 * a2;
    y3 = u3 * a1s * a1 + 3.0f * u2 * a1 * a2 + g1 * a3;
    y4 = u4 * a1s * a1s + 6.0f * u3 * a1s * a2
       + u2 * (3.0f * a2 * a2 + 4.0f * a1 * a3) + g1 * a4;
}

// One 128->128 hidden layer applied to 4 point-jets (group g), thread = unit j.
__device__ __forceinline__ void hidden_layer(
    const float* __restrict__ Wsh, const float* __restrict__ Bsh,
    const float4* __restrict__ in4, const float* __restrict__ in1,
    int j, int g,
    float (&y0)[4], float (&y1)[4], float (&y2)[4], float (&y3)[4], float (&y4)[4])
{
    float bj = Bsh[j];
    float c0[4], c1[4], c2[4], c3[4], c4[4];
#pragma unroll
    for (int q = 0; q < 4; q++) { c0[q] = bj; c1[q] = 0.f; c2[q] = 0.f; c3[q] = 0.f; c4[q] = 0.f; }
    const float4* in4g = in4 + g * 4 * 128;
    const float*  in1g = in1 + g * 4 * 128;
#pragma unroll 4
    for (int i = 0; i < 128; i++) {
        float wv = Wsh[i * 128 + j];
#pragma unroll
        for (int q = 0; q < 4; q++) {
            float4 h = in4g[q * 128 + i];
            float  h5 = in1g[q * 128 + i];
            c0[q] = fmaf(wv, h.x, c0[q]);
            c1[q] = fmaf(wv, h.y, c1[q]);
            c2[q] = fmaf(wv, h.z, c2[q]);
            c3[q] = fmaf(wv, h.w, c3[q]);
            c4[q] = fmaf(wv, h5,  c4[q]);
        }
    }
#pragma unroll
    for (int q = 0; q < 4; q++)
        tanh_jet(c0[q], c1[q], c2[q], c3[q], c4[q],
                 y0[q], y1[q], y2[q], y3[q], y4[q]);
}

// ============================================================================
// Main kernel: persistent blocks, 256 threads (2 groups x 128 units),
// 8 points per chunk (4 per group).
// ============================================================================
__global__ void __launch_bounds__(256, 1)
pinn_main(const float* __restrict__ W0, const float* __restrict__ b0,
          const float* __restrict__ W1, const float* __restrict__ b1,
          const float* __restrict__ W2, const float* __restrict__ b2,
          const float* __restrict__ W3, const float* __restrict__ b3,
          const float* __restrict__ x,  const float* __restrict__ data_x,
          float* __restrict__ out)
{
    extern __shared__ char sm[];
    float4* HA4 = (float4*)(sm + SM_HA4);
    float4* HB4 = (float4*)(sm + SM_HB4);
    float*  HA1 = (float*)(sm + SM_HA1);
    float*  HB1 = (float*)(sm + SM_HB1);
    float*  sW1 = (float*)(sm + SM_W1);
    float*  sW2 = (float*)(sm + SM_W2);
    float*  sW0 = (float*)(sm + SM_W0);
    float*  sW3 = (float*)(sm + SM_W3);
    float*  sB0 = (float*)(sm + SM_B0);
    float*  sB1 = (float*)(sm + SM_B1);
    float*  sB2 = (float*)(sm + SM_B2);
    float*  sB3 = (float*)(sm + SM_B3);
    float*  SS  = (float*)(sm + SM_SS);
    float*  RED = (float*)(sm + SM_RED);
    float*  DFIN= (float*)(sm + SM_DFIN);

    const int tid  = threadIdx.x;
    const int g    = tid >> 7;        // group 0/1
    const int j    = tid & 127;       // hidden unit
    const int lane = tid & 31;
    const int warp = tid >> 5;

    for (int i = tid; i < 16384; i += 256) { sW1[i] = W1[i]; sW2[i] = W2[i]; }
    if (tid < 128) {
        sW0[tid] = W0[tid]; sW3[tid] = W3[tid];
        sB0[tid] = b0[tid]; sB1[tid] = b1[tid]; sB2[tid] = b2[tid];
    }
    if (tid == 0) sB3[0] = b3[0];
    __syncthreads();

    // output scale constants (compile-time folded doubles -> f32)
    const float CW  = (float)(kWC);            // W_C / X_C^k for w, dw, ddddw
    const float CM  = (float)(-kEI * kWC);     // -EI*W_C/X_C^2 (== /X_C^3 since X_C=1)

    for (int chunk = blockIdx.x; chunk < NCHUNKS; chunk += gridDim.x) {
        const int pbase = chunk * 8;

        if (tid < 8) {
            int p = pbase + tid;
            float s = 0.0f;
            if (p < NPTS)                          s = x[p];
            else if (p < NPTS + NDATA)             s = data_x[p - NPTS];
            else if (p < NPTS + NDATA + NQUAD)     s = g_tn[p - NPTS - NDATA];
            else if (p == NPTS + NDATA + NQUAD + 1) s = 1.0f;   // s=0 for p==...+NQUAD
            SS[tid] = s;
        }
        __syncthreads();

        // ------ layer 0 (1 -> 128) + tanh jet ------
        {
            float w0j = sW0[j];
            float b0j = sB0[j];
#pragma unroll
            for (int q = 0; q < 4; q++) {
                int pt = g * 4 + q;
                float s  = SS[pt];
                float a0 = fmaf(w0j, s, b0j);
                float a1 = w0j;
                float y0v, y1v, y2v, y3v, y4v;
                tanh_jet(a0, a1, 0.f, 0.f, 0.f, y0v, y1v, y2v, y3v, y4v);
                HA4[pt * 128 + j] = make_float4(y0v, y1v, y2v, y3v);
                HA1[pt * 128 + j] = y4v;
            }
        }
        __syncthreads();

        // ------ layer 1 ------
        float y0[4], y1[4], y2[4], y3[4], y4[4];
        hidden_layer(sW1, sB1, HA4, HA1, j, g, y0, y1, y2, y3, y4);
#pragma unroll
        for (int q = 0; q < 4; q++) {
            int pt = g * 4 + q;
            HB4[pt * 128 + j] = make_float4(y0[q], y1[q], y2[q], y3[q]);
            HB1[pt * 128 + j] = y4[q];
        }
        __syncthreads();

        // ------ layer 2 (output stays in registers) ------
        hidden_layer(sW2, sB2, HB4, HB1, j, g, y0, y1, y2, y3, y4);

        // ------ head (128 -> 1): block reduction, fixed order ------
        {
            float w3j = sW3[j];
#pragma unroll
            for (int q = 0; q < 4; q++) {
                float v[5] = { w3j * y0[q], w3j * y1[q], w3j * y2[q],
                               w3j * y3[q], w3j * y4[q] };
#pragma unroll
                for (int c = 0; c < 5; c++) {
                    float t = v[c];
                    t += __shfl_xor_sync(0xffffffffu, t, 16);
                    t += __shfl_xor_sync(0xffffffffu, t, 8);
                    t += __shfl_xor_sync(0xffffffffu, t, 4);
                    t += __shfl_xor_sync(0xffffffffu, t, 2);
                    t += __shfl_xor_sync(0xffffffffu, t, 1);
                    if (lane == 0)
                        RED[((g * 4 + q) * 5 + c) * 4 + (warp & 3)] = t;
                }
            }
        }
        __syncthreads();

        if (tid < 40) {
            float v = RED[tid * 4 + 0] + RED[tid * 4 + 1]
                    + RED[tid * 4 + 2] + RED[tid * 4 + 3];
            if ((tid % 5) == 0) v += sB3[0];
            DFIN[tid] = v;
        }
        __syncthreads();

        if (tid < 8) {
            int p = pbase + tid;
            if (p < TOTALP) {
                float d0 = DFIN[tid * 5 + 0];
                float d1 = DFIN[tid * 5 + 1];
                float d2 = DFIN[tid * 5 + 2];
                float d3 = DFIN[tid * 5 + 3];
                float d4 = DFIN[tid * 5 + 4];
                if (p < NPTS) {
                    out[p]             = CW * d0;          // w * W_C
                    out[NPTS + p]      = CW * d1;          // dw * W_C / X_C
                    out[2 * NPTS + p]  = CM * d2;          // M
                    out[3 * NPTS + p]  = CM * d3;          // Q
                    out[4 * NPTS + p]  = CW * d4;          // ddddw * W_C
                } else if (p < NPTS + NDATA) {
                    g_pred[p - NPTS] = d0;
                } else if (p < NPTS + NDATA + NQUAD) {
                    g_fsq[p - NPTS - NDATA] = d2 * d2;
                } else if (p == NPTS + NDATA + NQUAD) {
                    g_bdry[0] = d0; g_bdry[1] = d1; g_bdry[2] = d2;
                    g_bdry[3] = d3; g_bdry[4] = d4;
                } else {
                    g_bdry[5] = d0; g_bdry[6] = d1; g_bdry[7] = d2;
                    g_bdry[8] = d3; g_bdry[9] = d4;
                }
            }
        }
        __syncthreads();
    }
}

// ============================================================================
// Finalize: deterministic reductions + scalar loss
// ============================================================================
__global__ void __launch_bounds__(256)
pinn_finalize(const float* __restrict__ data_w, float* __restrict__ out)
{
    __shared__ double sd[256];
    const int tid = threadIdx.x;

    // sum of fsq
    double acc = 0.0;
    for (int i = tid; i < NQUAD; i += 256) acc += (double)g_fsq[i];
    sd[tid] = acc;
    __syncthreads();
    for (int off = 128; off > 0; off >>= 1) {
        if (tid < off) sd[tid] += sd[tid + off];
        __syncthreads();
    }
    double S_fsq = sd[0];
    __syncthreads();

    // data residual sum
    const float wcf = (float)kWC;   // 1.5f
    double accd = 0.0;
    for (int i = tid; i < NDATA; i += 256) {
        float r = g_pred[i] - data_w[i] / wcf;
        accd += (double)(r * r);
    }
    sd[tid] = accd;
    __syncthreads();
    for (int off = 128; off > 0; off >>= 1) {
        if (tid < off) sd[tid] += sd[tid + off];
        __syncthreads();
    }
    double S_data = sd[0];

    if (tid == 0) {
        float quad   = g_wsum * (float)S_fsq;                       // sum(wq)*sum(fsq)
        float inter  = (float)(0.5 * kEI * (kWC * kWC) * 0.5) * quad;
        float wL     = g_bdry[5];
        float exter  = (float)(5.0 * kWC) * wL;                     // F_LOAD * W_C * wL
        float res_pel = inter - exter;

        float w0v = g_bdry[0], dw0 = g_bdry[1];
        float res_dir = (w0v * w0v + dw0 * dw0) * 0.5f;

        float ddwL = g_bdry[7], dddwL = g_bdry[8];
        float Fb   = (float)(-kEI * kWC) * dddwL;
        float tnn  = Fb / 5.0f - 1.0f;
        float res_neu = (tnn * tnn + ddwL * ddwL) * 0.5f;

        float res_data = (float)(S_data / (double)NDATA);

        out[5 * NPTS] = res_pel + (res_dir + res_neu) * 0.5f + res_data;
    }
}

// ============================================================================
// kernel_launch
// ============================================================================
extern "C" void kernel_launch(void* const* d_in, const int* in_sizes, int n_in,
                              void* d_out, int out_size)
{
    (void)n_in; (void)out_size;
    const float *W0, *b0, *W1, *b1, *W2, *b2, *W3, *b3, *x, *dxp, *dwp;
    if (in_sizes[0] == NPTS) {
        // signature order: x, data_x, data_w, W0, b0, W1, b1, W2, b2, W3, b3
        x   = (const float*)d_in[0];
        dxp = (const float*)d_in[1];
        dwp = (const float*)d_in[2];
        W0  = (const float*)d_in[3];  b0 = (const float*)d_in[4];
        W1  = (const float*)d_in[5];  b1 = (const float*)d_in[6];
        W2  = (const float*)d_in[7];  b2 = (const float*)d_in[8];
        W3  = (const float*)d_in[9];  b3 = (const float*)d_in[10];
    } else {
        // dict order: W0, b0, W1, b1, W2, b2, W3, b3, x, data_x, data_w
        W0  = (const float*)d_in[0];  b0 = (const float*)d_in[1];
        W1  = (const float*)d_in[2];  b1 = (const float*)d_in[3];
        W2  = (const float*)d_in[4];  b2 = (const float*)d_in[5];
        W3  = (const float*)d_in[6];  b3 = (const float*)d_in[7];
        x   = (const float*)d_in[8];
        dxp = (const float*)d_in[9];
        dwp = (const float*)d_in[10];
    }

    // ship quadrature tables (host-precomputed at static init)
    cudaMemcpyToSymbolAsync(g_tn,   g_gl.tn,    sizeof(float) * NQUAD, 0,
                            cudaMemcpyHostToDevice, 0);
    cudaMemcpyToSymbolAsync(g_wsum, &g_gl.wsum, sizeof(float), 0,
                            cudaMemcpyHostToDevice, 0);

    int sms = 148;
    cudaDeviceGetAttribute(&sms, cudaDevAttrMultiProcessorCount, 0);

    cudaFuncSetAttribute(pinn_main, cudaFuncAttributeMaxDynamicSharedMemorySize,
                         SMEM_BYTES);

    pinn_main<<<sms, 256, SMEM_BYTES>>>(W0, b0, W1, b1, W2, b2, W3, b3,
                                        x, dxp, (float*)d_out);
    pinn_finalize<<<1, 256>>>(dwp, (float*)d_out);
}

// round 2
// speedup vs baseline: 1.1989x; 1.1989x over previous
#include <cuda_runtime.h>
#include <cmath>
#include <cstdint>

// ============================================================================
// Problem constants
// ============================================================================
#define NPTS   32768
#define NDATA  1024
#define NQUAD  1000
#define TOTALP (NPTS + NDATA + NQUAD + 2)   // 34794
#define PCHUNK 16
#define NCHUNKS ((TOTALP + PCHUNK - 1) / PCHUNK)   // 2175

static constexpr double kEI = 5.0e7 * (((0.02 * 0.02 * 0.02) * 0.02) / 12.0); // EI
static constexpr double kWC = 1.0 / kEI;                                       // W_C (X_C = 1)

// ============================================================================
// Device globals (scratch — no allocation allowed)
// ============================================================================
__device__ float g_tn[NQUAD];     // transformed quadrature nodes 0.5*x + 0.5 (f32)
__device__ float g_wsum;          // sum of f32 quadrature weights
__device__ float g_fsq[NQUAD];    // (w'')^2 at quadrature nodes
__device__ float g_pred[NDATA];   // MLP prediction at data points
__device__ float g_bdry[10];      // jets at s=0 (0..4) and s=1 (5..9)

// ============================================================================
// Host-side Gauss-Legendre nodes/weights (double Newton, static init)
// ============================================================================
struct GLTables {
    float tn[NQUAD];
    float wsum;
    GLTables() {
        const int n = NQUAD;
        const double pi = 3.14159265358979323846;
        double sumw = 0.0;
        for (int k = 0; k < n; k++) {
            double x = cos(pi * (k + 0.75) / (n + 0.5));
            for (int it = 0; it < 100; it++) {
                double p0 = 1.0, p1 = x;
                for (int m = 2; m <= n; m++) {
                    double p2 = ((2.0 * m - 1.0) * x * p1 - (m - 1.0) * p0) / m;
                    p0 = p1; p1 = p2;
                }
                double dp = n * (x * p1 - p0) / (x * x - 1.0);
                double dx = p1 / dp;
                x -= dx;
                if (fabs(dx) < 1e-15) break;
            }
            double p0 = 1.0, p1 = x;
            for (int m = 2; m <= n; m++) {
                double p2 = ((2.0 * m - 1.0) * x * p1 - (m - 1.0) * p0) / m;
                p0 = p1; p1 = p2;
            }
            double dp = n * (x * p1 - p0) / (x * x - 1.0);
            double w = 2.0 / ((1.0 - x * x) * dp * dp);
            sumw += (double)(float)w;                 // sum of f32-rounded weights
            tn[k] = (float)(0.5 * x + 0.5);
        }
        wsum = (float)sumw;
    }
};
static GLTables g_gl;   // static init, host side

// ============================================================================
// Shared memory layout (dynamic).  Jets stored as point-PAIRS:
//   A01[pair][i] : float4 {c0_even, c0_odd, c1_even, c1_odd}
//   A23[pair][i] : float4 {c2_even, c2_odd, c3_even, c3_odd}
//   A4 [pair][i] : float2 {c4_even, c4_odd}
// 8 pairs total per chunk (4 per group of 128 threads).
// ============================================================================
static constexpr int SM_W1    = 0;          // 65536
static constexpr int SM_W2    = 65536;      // 65536
static constexpr int SM_HA01  = 131072;     // 8*128*16 = 16384
static constexpr int SM_HA23  = 147456;     // 16384
static constexpr int SM_HA4   = 163840;     // 8*128*8  = 8192
static constexpr int SM_HB01  = 172032;     // 16384
static constexpr int SM_HB23  = 188416;     // 16384
static constexpr int SM_HB4   = 204800;     // 8192
static constexpr int SM_W0    = 212992;     // 512
static constexpr int SM_W3    = 213504;     // 512
static constexpr int SM_B0    = 214016;     // 512
static constexpr int SM_B1    = 214528;     // 512
static constexpr int SM_B2    = 215040;     // 512
static constexpr int SM_B3    = 215552;     // 16
static constexpr int SM_SS    = 215568;     // 64
static constexpr int SM_RED   = 215632;     // 16*5*4*4 = 1280
static constexpr int SM_DFIN  = 216912;     // 16*5*4   = 320
static constexpr int SMEM_BYTES = 217232;

// ============================================================================
// tanh jet (Faa di Bruno), scalar
// ============================================================================
__device__ __forceinline__ void tanh_jet(float a0, float a1, float a2, float a3, float a4,
                                         float& y0, float& y1, float& y2, float& y3, float& y4)
{
    float t  = tanhf(a0);
    float t2 = t * t;
    float g1 = 1.0f - t2;                         // u'
    float u2 = -2.0f * t * g1;                    // u''
    float u3 = g1 * (6.0f * t2 - 2.0f);           // u'''
    float u4 = g1 * (16.0f * t - 24.0f * t2 * t); // u''''
    float a1s = a1 * a1;
    y0 = t;
    y1 = g1 * a1;
    y2 = u2 * a1s + g1 * a2;
    y3 = u3 * a1s * a1 + 3.0f * u2 * a1 * a2 + g1 * a3;
    y4 = u4 * a1s * a1s + 6.0f * u3 * a1s * a2
       + u2 * (3.0f * a2 * a2 + 4.0f * a1 * a3) + g1 * a4;
}

#define FMA2(acc, a, b) \
    asm("fma.rn.f32x2 %0, %1, %2, %0;" : "+l"(acc) : "l"(a), "l"(b))

// ============================================================================
// One 128->128 hidden layer for 8 points (4 pairs) of one group.
// a01/a23/a4: shared-window addresses of the group's pair-0 row.
// Outputs UNPACKED jets y[c][k], k = local point 0..7.
// ============================================================================
__device__ __forceinline__ void hidden_layer_p(
    const float* __restrict__ Wsh, const float* __restrict__ Bsh,
    uint32_t a01, uint32_t a23, uint32_t a4,
    int j, float (&y)[5][8])
{
    unsigned long long acc[5][4];
    {
        float bj = Bsh[j];
        unsigned long long b2;
        asm("mov.b64 %0, {%1, %1};" : "=l"(b2) : "f"(bj));
#pragma unroll
        for (int p = 0; p < 4; p++) {
            acc[0][p] = b2;
            acc[1][p] = 0ull; acc[2][p] = 0ull; acc[3][p] = 0ull; acc[4][p] = 0ull;
        }
    }
#pragma unroll 4
    for (int i = 0; i < 128; i++) {
        float wv = Wsh[i * 128 + j];
        unsigned long long w2;
        asm("mov.b64 %0, {%1, %1};" : "=l"(w2) : "f"(wv));
        uint32_t o01 = a01 + i * 16;
        uint32_t o23 = a23 + i * 16;
        uint32_t o4  = a4  + i * 8;
#pragma unroll
        for (int p = 0; p < 4; p++) {
            unsigned long long h0, h1, h2, h3, h4v;
            asm volatile("ld.shared.v2.b64 {%0, %1}, [%2];"
                         : "=l"(h0), "=l"(h1) : "r"(o01 + p * 2048));
            asm volatile("ld.shared.v2.b64 {%0, %1}, [%2];"
                         : "=l"(h2), "=l"(h3) : "r"(o23 + p * 2048));
            asm volatile("ld.shared.b64 %0, [%1];"
                         : "=l"(h4v) : "r"(o4 + p * 1024));
            FMA2(acc[0][p], w2, h0);
            FMA2(acc[1][p], w2, h1);
            FMA2(acc[2][p], w2, h2);
            FMA2(acc[3][p], w2, h3);
            FMA2(acc[4][p], w2, h4v);
        }
    }
#pragma unroll
    for (int p = 0; p < 4; p++) {
        float ae[5], ao[5];
#pragma unroll
        for (int c = 0; c < 5; c++)
            asm("mov.b64 {%0, %1}, %2;" : "=f"(ae[c]), "=f"(ao[c]) : "l"(acc[c][p]));
        tanh_jet(ae[0], ae[1], ae[2], ae[3], ae[4],
                 y[0][2 * p], y[1][2 * p], y[2][2 * p], y[3][2 * p], y[4][2 * p]);
        tanh_jet(ao[0], ao[1], ao[2], ao[3], ao[4],
                 y[0][2 * p + 1], y[1][2 * p + 1], y[2][2 * p + 1], y[3][2 * p + 1], y[4][2 * p + 1]);
    }
}

// Store jets y[c][k] (k=0..7) of this thread's unit j into pair-layout smem.
__device__ __forceinline__ void store_jets(
    float4* H01, float4* H23, float2* H4, int gpair0, int j, const float (&y)[5][8])
{
#pragma unroll
    for (int p = 0; p < 4; p++) {
        int idx = (gpair0 + p) * 128 + j;
        H01[idx] = make_float4(y[0][2*p], y[0][2*p+1], y[1][2*p], y[1][2*p+1]);
        H23[idx] = make_float4(y[2][2*p], y[2][2*p+1], y[3][2*p], y[3][2*p+1]);
        H4 [idx] = make_float2(y[4][2*p], y[4][2*p+1]);
    }
}

// ============================================================================
// Main kernel: persistent blocks, 256 threads (2 groups x 128 units),
// 16 points per chunk (8 per group, 4 pairs).
// ============================================================================
__global__ void __launch_bounds__(256, 1)
pinn_main(const float* __restrict__ W0, const float* __restrict__ b0,
          const float* __restrict__ W1, const float* __restrict__ b1,
          const float* __restrict__ W2, const float* __restrict__ b2,
          const float* __restrict__ W3, const float* __restrict__ b3,
          const float* __restrict__ x,  const float* __restrict__ data_x,
          float* __restrict__ out)
{
    extern __shared__ char sm[];
    float*  sW1 = (float*)(sm + SM_W1);
    float*  sW2 = (float*)(sm + SM_W2);
    float4* HA01 = (float4*)(sm + SM_HA01);
    float4* HA23 = (float4*)(sm + SM_HA23);
    float2* HA4  = (float2*)(sm + SM_HA4);
    float4* HB01 = (float4*)(sm + SM_HB01);
    float4* HB23 = (float4*)(sm + SM_HB23);
    float2* HB4  = (float2*)(sm + SM_HB4);
    float*  sW0 = (float*)(sm + SM_W0);
    float*  sW3 = (float*)(sm + SM_W3);
    float*  sB0 = (float*)(sm + SM_B0);
    float*  sB1 = (float*)(sm + SM_B1);
    float*  sB2 = (float*)(sm + SM_B2);
    float*  sB3 = (float*)(sm + SM_B3);
    float*  SS  = (float*)(sm + SM_SS);
    float*  RED = (float*)(sm + SM_RED);
    float*  DFIN= (float*)(sm + SM_DFIN);

    const int tid  = threadIdx.x;
    const int g    = tid >> 7;        // group 0/1
    const int j    = tid & 127;       // hidden unit
    const int lane = tid & 31;
    const int warp = tid >> 5;

    const uint32_t smw = (uint32_t)__cvta_generic_to_shared(sm);
    const uint32_t aA01 = smw + SM_HA01 + g * 4 * 2048;
    const uint32_t aA23 = smw + SM_HA23 + g * 4 * 2048;
    const uint32_t aA4  = smw + SM_HA4  + g * 4 * 1024;
    const uint32_t aB01 = smw + SM_HB01 + g * 4 * 2048;
    const uint32_t aB23 = smw + SM_HB23 + g * 4 * 2048;
    const uint32_t aB4  = smw + SM_HB4  + g * 4 * 1024;

    for (int i = tid; i < 16384; i += 256) { sW1[i] = W1[i]; sW2[i] = W2[i]; }
    if (tid < 128) {
        sW0[tid] = W0[tid]; sW3[tid] = W3[tid];
        sB0[tid] = b0[tid]; sB1[tid] = b1[tid]; sB2[tid] = b2[tid];
    }
    if (tid == 0) sB3[0] = b3[0];
    __syncthreads();

    const float CW  = (float)(kWC);            // W_C scale
    const float CM  = (float)(-kEI * kWC);     // moment/force scale

    for (int chunk = blockIdx.x; chunk < NCHUNKS; chunk += gridDim.x) {
        const int pbase = chunk * PCHUNK;

        if (tid < PCHUNK) {
            int p = pbase + tid;
            float s = 0.0f;
            if (p < NPTS)                           s = x[p];
            else if (p < NPTS + NDATA)              s = data_x[p - NPTS];
            else if (p < NPTS + NDATA + NQUAD)      s = g_tn[p - NPTS - NDATA];
            else if (p == NPTS + NDATA + NQUAD + 1) s = 1.0f;  // s=0 for the other bdry
            SS[tid] = s;
        }
        __syncthreads();

        // ------ layer 0 (1 -> 128) + tanh jet ------
        {
            float w0j = sW0[j];
            float b0j = sB0[j];
            float y[5][8];
#pragma unroll
            for (int k = 0; k < 8; k++) {
                float s  = SS[g * 8 + k];
                float a0 = fmaf(w0j, s, b0j);
                tanh_jet(a0, w0j, 0.f, 0.f, 0.f,
                         y[0][k], y[1][k], y[2][k], y[3][k], y[4][k]);
            }
            store_jets(HA01, HA23, HA4, g * 4, j, y);
        }
        __syncthreads();

        // ------ layer 1 ------
        {
            float y[5][8];
            hidden_layer_p(sW1, sB1, aA01, aA23, aA4, j, y);
            store_jets(HB01, HB23, HB4, g * 4, j, y);
        }
        __syncthreads();

        // ------ layer 2 (outputs stay in registers) ------
        float y[5][8];
        hidden_layer_p(sW2, sB2, aB01, aB23, aB4, j, y);

        // ------ head (128 -> 1): warp shuffle + smem tree, fixed order ------
        {
            float w3j = sW3[j];
#pragma unroll
            for (int k = 0; k < 8; k++) {
                int pt = g * 8 + k;
#pragma unroll
                for (int c = 0; c < 5; c++) {
                    float t = w3j * y[c][k];
                    t += __shfl_xor_sync(0xffffffffu, t, 16);
                    t += __shfl_xor_sync(0xffffffffu, t, 8);
                    t += __shfl_xor_sync(0xffffffffu, t, 4);
                    t += __shfl_xor_sync(0xffffffffu, t, 2);
                    t += __shfl_xor_sync(0xffffffffu, t, 1);
                    if (lane == 0)
                        RED[(pt * 5 + c) * 4 + (warp & 3)] = t;
                }
            }
        }
        __syncthreads();

        if (tid < 80) {
            float v = RED[tid * 4 + 0] + RED[tid * 4 + 1]
                    + RED[tid * 4 + 2] + RED[tid * 4 + 3];
            if ((tid % 5) == 0) v += sB3[0];
            DFIN[tid] = v;
        }
        __syncthreads();

        if (tid < PCHUNK) {
            int p = pbase + tid;
            if (p < TOTALP) {
                float d0 = DFIN[tid * 5 + 0];
                float d1 = DFIN[tid * 5 + 1];
                float d2 = DFIN[tid * 5 + 2];
                float d3 = DFIN[tid * 5 + 3];
                float d4 = DFIN[tid * 5 + 4];
                if (p < NPTS) {
                    out[p]             = CW * d0;
                    out[NPTS + p]      = CW * d1;
                    out[2 * NPTS + p]  = CM * d2;
                    out[3 * NPTS + p]  = CM * d3;
                    out[4 * NPTS + p]  = CW * d4;
                } else if (p < NPTS + NDATA) {
                    g_pred[p - NPTS] = d0;
                } else if (p < NPTS + NDATA + NQUAD) {
                    g_fsq[p - NPTS - NDATA] = d2 * d2;
                } else if (p == NPTS + NDATA + NQUAD) {
                    g_bdry[0] = d0; g_bdry[1] = d1; g_bdry[2] = d2;
                    g_bdry[3] = d3; g_bdry[4] = d4;
                } else {
                    g_bdry[5] = d0; g_bdry[6] = d1; g_bdry[7] = d2;
                    g_bdry[8] = d3; g_bdry[9] = d4;
                }
            }
        }
        __syncthreads();
    }
}

// ============================================================================
// Finalize: deterministic reductions + scalar loss
// ============================================================================
__global__ void __launch_bounds__(256)
pinn_finalize(const float* __restrict__ data_w, float* __restrict__ out)
{
    __shared__ double sd[256];
    const int tid = threadIdx.x;

    double acc = 0.0;
    for (int i = tid; i < NQUAD; i += 256) acc += (double)g_fsq[i];
    sd[tid] = acc;
    __syncthreads();
    for (int off = 128; off > 0; off >>= 1) {
        if (tid < off) sd[tid] += sd[tid + off];
        __syncthreads();
    }
    double S_fsq = sd[0];
    __syncthreads();

    const float wcf = (float)kWC;
    double accd = 0.0;
    for (int i = tid; i < NDATA; i += 256) {
        float r = g_pred[i] - data_w[i] / wcf;
        accd += (double)(r * r);
    }
    sd[tid] = accd;
    __syncthreads();
    for (int off = 128; off > 0; off >>= 1) {
        if (tid < off) sd[tid] += sd[tid + off];
        __syncthreads();
    }
    double S_data = sd[0];

    if (tid == 0) {
        float quad   = g_wsum * (float)S_fsq;
        float inter  = (float)(0.5 * kEI * (kWC * kWC) * 0.5) * quad;
        float wL     = g_bdry[5];
        float exter  = (float)(5.0 * kWC) * wL;
        float res_pel = inter - exter;

        float w0v = g_bdry[0], dw0 = g_bdry[1];
        float res_dir = (w0v * w0v + dw0 * dw0) * 0.5f;

        float ddwL = g_bdry[7], dddwL = g_bdry[8];
        float Fb   = (float)(-kEI * kWC) * dddwL;
        float tnn  = Fb / 5.0f - 1.0f;
        float res_neu = (tnn * tnn + ddwL * ddwL) * 0.5f;

        float res_data = (float)(S_data / (double)NDATA);

        out[5 * NPTS] = res_pel + (res_dir + res_neu) * 0.5f + res_data;
    }
}

// ============================================================================
// kernel_launch
// ============================================================================
extern "C" void kernel_launch(void* const* d_in, const int* in_sizes, int n_in,
                              void* d_out, int out_size)
{
    (void)n_in; (void)out_size;
    const float *W0, *b0, *W1, *b1, *W2, *b2, *W3, *b3, *x, *dxp, *dwp;
    if (in_sizes[0] == NPTS) {
        x   = (const float*)d_in[0];
        dxp = (const float*)d_in[1];
        dwp = (const float*)d_in[2];
        W0  = (const float*)d_in[3];  b0 = (const float*)d_in[4];
        W1  = (const float*)d_in[5];  b1 = (const float*)d_in[6];
        W2  = (const float*)d_in[7];  b2 = (const float*)d_in[8];
        W3  = (const float*)d_in[9];  b3 = (const float*)d_in[10];
    } else {
        W0  = (const float*)d_in[0];  b0 = (const float*)d_in[1];
        W1  = (const float*)d_in[2];  b1 = (const float*)d_in[3];
        W2  = (const float*)d_in[4];  b2 = (const float*)d_in[5];
        W3  = (const float*)d_in[6];  b3 = (const float*)d_in[7];
        x   = (const float*)d_in[8];
        dxp = (const float*)d_in[9];
        dwp = (const float*)d_in[10];
    }

    cudaMemcpyToSymbolAsync(g_tn,   g_gl.tn,    sizeof(float) * NQUAD, 0,
                            cudaMemcpyHostToDevice, 0);
    cudaMemcpyToSymbolAsync(g_wsum, &g_gl.wsum, sizeof(float), 0,
                            cudaMemcpyHostToDevice, 0);

    int sms = 148;
    cudaDeviceGetAttribute(&sms, cudaDevAttrMultiProcessorCount, 0);

    cudaFuncSetAttribute(pinn_main, cudaFuncAttributeMaxDynamicSharedMemorySize,
                         SMEM_BYTES);

    pinn_main<<<sms, 256, SMEM_BYTES>>>(W0, b0, W1, b1, W2, b2, W3, b3,
                                        x, dxp, (float*)d_out);
    pinn_finalize<<<1, 256>>>(dwp, (float*)d_out);
}

// round 3
// speedup vs baseline: 2.0089x; 1.6756x over previous
#include <cuda_runtime.h>
#include <cmath>
#include <cstdint>

typedef unsigned long long ull;

// ============================================================================
// Problem constants
// ============================================================================
#define NPTS   32768
#define NDATA  1024
#define NQUAD  1000
#define TOTALP (NPTS + NDATA + NQUAD + 2)   // 34794 (even)
#define NPAIRS (TOTALP / 2)                 // 17397

static constexpr double kEI = 5.0e7 * (((0.02 * 0.02 * 0.02) * 0.02) / 12.0); // EI
static constexpr double kWC = 1.0 / kEI;                                       // W_C

// ============================================================================
// Device globals (scratch)
// ============================================================================
__device__ float g_tn[NQUAD];
__device__ float g_wsum;
__device__ float g_fsq[NQUAD];
__device__ float g_pred[NDATA];
__device__ float g_bdry[10];

// ============================================================================
// Host-side Gauss-Legendre tables (static init)
// ============================================================================
struct GLTables {
    float tn[NQUAD];
    float wsum;
    GLTables() {
        const int n = NQUAD;
        const double pi = 3.14159265358979323846;
        double sumw = 0.0;
        for (int k = 0; k < n; k++) {
            double x = cos(pi * (k + 0.75) / (n + 0.5));
            for (int it = 0; it < 100; it++) {
                double p0 = 1.0, p1 = x;
                for (int m = 2; m <= n; m++) {
                    double p2 = ((2.0 * m - 1.0) * x * p1 - (m - 1.0) * p0) / m;
                    p0 = p1; p1 = p2;
                }
                double dp = n * (x * p1 - p0) / (x * x - 1.0);
                double dx = p1 / dp;
                x -= dx;
                if (fabs(dx) < 1e-15) break;
            }
            double p0 = 1.0, p1 = x;
            for (int m = 2; m <= n; m++) {
                double p2 = ((2.0 * m - 1.0) * x * p1 - (m - 1.0) * p0) / m;
                p0 = p1; p1 = p2;
            }
            double dp = n * (x * p1 - p0) / (x * x - 1.0);
            double w = 2.0 / ((1.0 - x * x) * dp * dp);
            sumw += (double)(float)w;
            tn[k] = (float)(0.5 * x + 0.5);
        }
        wsum = (float)sumw;
    }
};
static GLTables g_gl;

// ============================================================================
// Shared memory layout.  Per-warp jet buffers, pair layout:
//   A01[i]: float4 {c0_e, c0_o, c1_e, c1_o}   (16 B/row, 128 rows/warp)
//   A23[i]: float4 {c2_e, c2_o, c3_e, c3_o}
//   A4 [i]: float2 {c4_e, c4_o}               (8 B/row)
// ============================================================================
static constexpr int SM_W1   = 0;          // 65536
static constexpr int SM_W2   = 65536;      // 65536
static constexpr int SM_A01  = 131072;     // 8 warps * 2048 = 16384
static constexpr int SM_A23  = 147456;     // 16384
static constexpr int SM_A4   = 163840;     // 8 warps * 1024 =  8192
static constexpr int SM_B01  = 172032;     // 16384
static constexpr int SM_B23  = 188416;     // 16384
static constexpr int SM_B4   = 204800;     // 8192
static constexpr int SM_W0   = 212992;     // 512
static constexpr int SM_W3   = 213504;     // 512
static constexpr int SM_B0v  = 214016;     // 512
static constexpr int SM_B1v  = 214528;     // 512
static constexpr int SM_B2v  = 215040;     // 512
static constexpr int SM_B3v  = 215552;     // 16
static constexpr int SMEM_BYTES = 215568;

// ============================================================================
// tanh jet (Faa di Bruno)
// ============================================================================
__device__ __forceinline__ void tanh_jet(float a0, float a1, float a2, float a3, float a4,
                                         float& y0, float& y1, float& y2, float& y3, float& y4)
{
    float t  = tanhf(a0);
    float t2 = t * t;
    float g1 = 1.0f - t2;
    float u2 = -2.0f * t * g1;
    float u3 = g1 * (6.0f * t2 - 2.0f);
    float u4 = g1 * (16.0f * t - 24.0f * t2 * t);
    float a1s = a1 * a1;
    y0 = t;
    y1 = g1 * a1;
    y2 = u2 * a1s + g1 * a2;
    y3 = u3 * a1s * a1 + 3.0f * u2 * a1 * a2 + g1 * a3;
    y4 = u4 * a1s * a1s + 6.0f * u3 * a1s * a2
       + u2 * (3.0f * a2 * a2 + 4.0f * a1 * a3) + g1 * a4;
}

#define FMA2(acc, a, b) \
    asm("fma.rn.f32x2 %0, %1, %2, %0;" : "+l"(acc) : "l"(a), "l"(b))
#define PACK2(d, f) \
    asm("mov.b64 %0, {%1, %1};" : "=l"(d) : "f"(f))
#define UNPACK2(lo, hi, d) \
    asm("mov.b64 {%0, %1}, %2;" : "=f"(lo), "=f"(hi) : "l"(d))

// ============================================================================
// Warp-level 128->128 GEMM over one point-pair; thread t owns units 4t..4t+3.
// acc[c][u] packed {even, odd}.
// ============================================================================
__device__ __forceinline__ void gemm4(
    const float* __restrict__ Wsh, const float* __restrict__ Bsh,
    uint32_t a01, uint32_t a23, uint32_t a4, int t, ull (&acc)[5][4])
{
#pragma unroll
    for (int u = 0; u < 4; u++) {
        PACK2(acc[0][u], Bsh[4 * t + u]);
        acc[1][u] = 0ull; acc[2][u] = 0ull; acc[3][u] = 0ull; acc[4][u] = 0ull;
    }
#pragma unroll 4
    for (int i = 0; i < 128; i++) {
        const float4 wv = *reinterpret_cast<const float4*>(Wsh + i * 128 + 4 * t);
        ull h0, h1, h2, h3, h4v;
        asm volatile("ld.shared.v2.b64 {%0,%1},[%2];"
                     : "=l"(h0), "=l"(h1) : "r"(a01 + i * 16));
        asm volatile("ld.shared.v2.b64 {%0,%1},[%2];"
                     : "=l"(h2), "=l"(h3) : "r"(a23 + i * 16));
        asm volatile("ld.shared.b64 %0,[%1];"
                     : "=l"(h4v) : "r"(a4 + i * 8));
        ull w2;
        PACK2(w2, wv.x);
        FMA2(acc[0][0], w2, h0); FMA2(acc[1][0], w2, h1); FMA2(acc[2][0], w2, h2);
        FMA2(acc[3][0], w2, h3); FMA2(acc[4][0], w2, h4v);
        PACK2(w2, wv.y);
        FMA2(acc[0][1], w2, h0); FMA2(acc[1][1], w2, h1); FMA2(acc[2][1], w2, h2);
        FMA2(acc[3][1], w2, h3); FMA2(acc[4][1], w2, h4v);
        PACK2(w2, wv.z);
        FMA2(acc[0][2], w2, h0); FMA2(acc[1][2], w2, h1); FMA2(acc[2][2], w2, h2);
        FMA2(acc[3][2], w2, h3); FMA2(acc[4][2], w2, h4v);
        PACK2(w2, wv.w);
        FMA2(acc[0][3], w2, h0); FMA2(acc[1][3], w2, h1); FMA2(acc[2][3], w2, h2);
        FMA2(acc[3][3], w2, h3); FMA2(acc[4][3], w2, h4v);
    }
}

// tanh-jet the accumulators and store into pair-layout buffers (rows 4t..4t+3)
__device__ __forceinline__ void tanh_store(
    const ull (&acc)[5][4], int t,
    float4* __restrict__ D01, float4* __restrict__ D23, float2* __restrict__ D4)
{
#pragma unroll
    for (int u = 0; u < 4; u++) {
        float ae[5], ao[5], ye[5], yo[5];
#pragma unroll
        for (int c = 0; c < 5; c++) UNPACK2(ae[c], ao[c], acc[c][u]);
        tanh_jet(ae[0], ae[1], ae[2], ae[3], ae[4], ye[0], ye[1], ye[2], ye[3], ye[4]);
        tanh_jet(ao[0], ao[1], ao[2], ao[3], ao[4], yo[0], yo[1], yo[2], yo[3], yo[4]);
        int r = 4 * t + u;
        D01[r] = make_float4(ye[0], yo[0], ye[1], yo[1]);
        D23[r] = make_float4(ye[2], yo[2], ye[3], yo[3]);
        D4 [r] = make_float2(ye[4], yo[4]);
    }
}

// ============================================================================
// Main kernel: 256 threads = 8 independent warp-pipelines; each warp processes
// one point-PAIR at a time through the whole network. No block syncs in loop.
// ============================================================================
__global__ void __launch_bounds__(256, 1)
pinn_main(const float* __restrict__ W0, const float* __restrict__ b0,
          const float* __restrict__ W1, const float* __restrict__ b1,
          const float* __restrict__ W2, const float* __restrict__ b2,
          const float* __restrict__ W3, const float* __restrict__ b3,
          const float* __restrict__ x,  const float* __restrict__ data_x,
          float* __restrict__ out)
{
    extern __shared__ char sm[];
    float* sW1 = (float*)(sm + SM_W1);
    float* sW2 = (float*)(sm + SM_W2);
    float* sW0 = (float*)(sm + SM_W0);
    float* sW3 = (float*)(sm + SM_W3);
    float* sB0 = (float*)(sm + SM_B0v);
    float* sB1 = (float*)(sm + SM_B1v);
    float* sB2 = (float*)(sm + SM_B2v);
    float* sB3 = (float*)(sm + SM_B3v);

    const int tid  = threadIdx.x;
    const int warp = tid >> 5;
    const int t    = tid & 31;

    // per-warp buffer pointers
    float4* A01 = (float4*)(sm + SM_A01 + warp * 2048);
    float4* A23 = (float4*)(sm + SM_A23 + warp * 2048);
    float2* A4  = (float2*)(sm + SM_A4  + warp * 1024);
    float4* B01 = (float4*)(sm + SM_B01 + warp * 2048);
    float4* B23 = (float4*)(sm + SM_B23 + warp * 2048);
    float2* B4  = (float2*)(sm + SM_B4  + warp * 1024);

    const uint32_t smw  = (uint32_t)__cvta_generic_to_shared(sm);
    const uint32_t aA01 = smw + SM_A01 + warp * 2048;
    const uint32_t aA23 = smw + SM_A23 + warp * 2048;
    const uint32_t aA4  = smw + SM_A4  + warp * 1024;
    const uint32_t aB01 = smw + SM_B01 + warp * 2048;
    const uint32_t aB23 = smw + SM_B23 + warp * 2048;
    const uint32_t aB4  = smw + SM_B4  + warp * 1024;

    for (int i = tid; i < 16384; i += 256) { sW1[i] = W1[i]; sW2[i] = W2[i]; }
    if (tid < 128) {
        sW0[tid] = W0[tid]; sW3[tid] = W3[tid];
        sB0[tid] = b0[tid]; sB1[tid] = b1[tid]; sB2[tid] = b2[tid];
    }
    if (tid == 0) sB3[0] = b3[0];
    __syncthreads();

    const float CW = (float)(kWC);
    const float CM = (float)(-kEI * kWC);
    const float b3v = sB3[0];

    const int gw      = blockIdx.x * 8 + warp;
    const int nwarps  = gridDim.x * 8;

    for (int pair = gw; pair < NPAIRS; pair += nwarps) {
        const int p0 = pair * 2;

        // ------ fetch input coords (both points; same category by parity) ------
        float se, so;
        if (p0 < NPTS)                      { se = x[p0];               so = x[p0 + 1]; }
        else if (p0 < NPTS + NDATA)         { se = data_x[p0 - NPTS];   so = data_x[p0 + 1 - NPTS]; }
        else if (p0 < NPTS + NDATA + NQUAD) { int q = p0 - NPTS - NDATA; se = g_tn[q]; so = g_tn[q + 1]; }
        else                                { se = 0.0f;                so = 1.0f; }

        // ------ layer 0 (1 -> 128) ------
#pragma unroll
        for (int u = 0; u < 4; u++) {
            int r = 4 * t + u;
            float w0j = sW0[r], b0j = sB0[r];
            float ye[5], yo[5];
            tanh_jet(fmaf(w0j, se, b0j), w0j, 0.f, 0.f, 0.f,
                     ye[0], ye[1], ye[2], ye[3], ye[4]);
            tanh_jet(fmaf(w0j, so, b0j), w0j, 0.f, 0.f, 0.f,
                     yo[0], yo[1], yo[2], yo[3], yo[4]);
            A01[r] = make_float4(ye[0], yo[0], ye[1], yo[1]);
            A23[r] = make_float4(ye[2], yo[2], ye[3], yo[3]);
            A4 [r] = make_float2(ye[4], yo[4]);
        }
        __syncwarp();

        // ------ layer 1 ------
        {
            ull acc[5][4];
            gemm4(sW1, sB1, aA01, aA23, aA4, t, acc);
            tanh_store(acc, t, B01, B23, B4);
        }
        __syncwarp();

        // ------ layer 2 + head ------
        ull acc[5][4];
        gemm4(sW2, sB2, aB01, aB23, aB4, t, acc);

        float pe[5] = {0.f, 0.f, 0.f, 0.f, 0.f};
        float po[5] = {0.f, 0.f, 0.f, 0.f, 0.f};
#pragma unroll
        for (int u = 0; u < 4; u++) {
            float ae[5], ao[5], ye[5], yo[5];
#pragma unroll
            for (int c = 0; c < 5; c++) UNPACK2(ae[c], ao[c], acc[c][u]);
            tanh_jet(ae[0], ae[1], ae[2], ae[3], ae[4], ye[0], ye[1], ye[2], ye[3], ye[4]);
            tanh_jet(ao[0], ao[1], ao[2], ao[3], ao[4], yo[0], yo[1], yo[2], yo[3], yo[4]);
            float w3v = sW3[4 * t + u];
#pragma unroll
            for (int c = 0; c < 5; c++) {
                pe[c] = fmaf(w3v, ye[c], pe[c]);
                po[c] = fmaf(w3v, yo[c], po[c]);
            }
        }
        // fixed-order warp tree reduction
#pragma unroll
        for (int c = 0; c < 5; c++) {
#pragma unroll
            for (int off = 16; off > 0; off >>= 1) {
                pe[c] += __shfl_xor_sync(0xffffffffu, pe[c], off);
                po[c] += __shfl_xor_sync(0xffffffffu, po[c], off);
            }
        }

        if (t == 0) {
            float de[5], dd[5];
#pragma unroll
            for (int c = 0; c < 5; c++) { de[c] = pe[c]; dd[c] = po[c]; }
            de[0] += b3v; dd[0] += b3v;

            if (p0 < NPTS) {
                int p1 = p0 + 1;
                out[p0]            = CW * de[0];  out[p1]            = CW * dd[0];
                out[NPTS + p0]     = CW * de[1];  out[NPTS + p1]     = CW * dd[1];
                out[2*NPTS + p0]   = CM * de[2];  out[2*NPTS + p1]   = CM * dd[2];
                out[3*NPTS + p0]   = CM * de[3];  out[3*NPTS + p1]   = CM * dd[3];
                out[4*NPTS + p0]   = CW * de[4];  out[4*NPTS + p1]   = CW * dd[4];
            } else if (p0 < NPTS + NDATA) {
                int q = p0 - NPTS;
                g_pred[q]     = de[0];
                g_pred[q + 1] = dd[0];
            } else if (p0 < NPTS + NDATA + NQUAD) {
                int q = p0 - NPTS - NDATA;
                g_fsq[q]     = de[2] * de[2];
                g_fsq[q + 1] = dd[2] * dd[2];
            } else {
                g_bdry[0] = de[0]; g_bdry[1] = de[1]; g_bdry[2] = de[2];
                g_bdry[3] = de[3]; g_bdry[4] = de[4];
                g_bdry[5] = dd[0]; g_bdry[6] = dd[1]; g_bdry[7] = dd[2];
                g_bdry[8] = dd[3]; g_bdry[9] = dd[4];
            }
        }
        __syncwarp();
    }
}

// ============================================================================
// Finalize: deterministic reductions + scalar loss
// ============================================================================
__global__ void __launch_bounds__(256)
pinn_finalize(const float* __restrict__ data_w, float* __restrict__ out)
{
    __shared__ double sd[256];
    const int tid = threadIdx.x;

    double acc = 0.0;
    for (int i = tid; i < NQUAD; i += 256) acc += (double)g_fsq[i];
    sd[tid] = acc;
    __syncthreads();
    for (int off = 128; off > 0; off >>= 1) {
        if (tid < off) sd[tid] += sd[tid + off];
        __syncthreads();
    }
    double S_fsq = sd[0];
    __syncthreads();

    const float wcf = (float)kWC;
    double accd = 0.0;
    for (int i = tid; i < NDATA; i += 256) {
        float r = g_pred[i] - data_w[i] / wcf;
        accd += (double)(r * r);
    }
    sd[tid] = accd;
    __syncthreads();
    for (int off = 128; off > 0; off >>= 1) {
        if (tid < off) sd[tid] += sd[tid + off];
        __syncthreads();
    }
    double S_data = sd[0];

    if (tid == 0) {
        float quad   = g_wsum * (float)S_fsq;
        float inter  = (float)(0.5 * kEI * (kWC * kWC) * 0.5) * quad;
        float wL     = g_bdry[5];
        float exter  = (float)(5.0 * kWC) * wL;
        float res_pel = inter - exter;

        float w0v = g_bdry[0], dw0 = g_bdry[1];
        float res_dir = (w0v * w0v + dw0 * dw0) * 0.5f;

        float ddwL = g_bdry[7], dddwL = g_bdry[8];
        float Fb   = (float)(-kEI * kWC) * dddwL;
        float tnn  = Fb / 5.0f - 1.0f;
        float res_neu = (tnn * tnn + ddwL * ddwL) * 0.5f;

        float res_data = (float)(S_data / (double)NDATA);

        out[5 * NPTS] = res_pel + (res_dir + res_neu) * 0.5f + res_data;
    }
}

// ============================================================================
// kernel_launch
// ============================================================================
extern "C" void kernel_launch(void* const* d_in, const int* in_sizes, int n_in,
                              void* d_out, int out_size)
{
    (void)n_in; (void)out_size;
    const float *W0, *b0, *W1, *b1, *W2, *b2, *W3, *b3, *x, *dxp, *dwp;
    if (in_sizes[0] == NPTS) {
        x   = (const float*)d_in[0];
        dxp = (const float*)d_in[1];
        dwp = (const float*)d_in[2];
        W0  = (const float*)d_in[3];  b0 = (const float*)d_in[4];
        W1  = (const float*)d_in[5];  b1 = (const float*)d_in[6];
        W2  = (const float*)d_in[7];  b2 = (const float*)d_in[8];
        W3  = (const float*)d_in[9];  b3 = (const float*)d_in[10];
    } else {
        W0  = (const float*)d_in[0];  b0 = (const float*)d_in[1];
        W1  = (const float*)d_in[2];  b1 = (const float*)d_in[3];
        W2  = (const float*)d_in[4];  b2 = (const float*)d_in[5];
        W3  = (const float*)d_in[6];  b3 = (const float*)d_in[7];
        x   = (const float*)d_in[8];
        dxp = (const float*)d_in[9];
        dwp = (const float*)d_in[10];
    }

    cudaMemcpyToSymbolAsync(g_tn,   g_gl.tn,    sizeof(float) * NQUAD, 0,
                            cudaMemcpyHostToDevice, 0);
    cudaMemcpyToSymbolAsync(g_wsum, &g_gl.wsum, sizeof(float), 0,
                            cudaMemcpyHostToDevice, 0);

    int sms = 148;
    cudaDeviceGetAttribute(&sms, cudaDevAttrMultiProcessorCount, 0);

    cudaFuncSetAttribute(pinn_main, cudaFuncAttributeMaxDynamicSharedMemorySize,
                         SMEM_BYTES);

    pinn_main<<<sms, 256, SMEM_BYTES>>>(W0, b0, W1, b1, W2, b2, W3, b3,
                                        x, dxp, (float*)d_out);
    pinn_finalize<<<1, 256>>>(dwp, (float*)d_out);
}